// round 5
// baseline (speedup 1.0000x reference)
#include <cuda_runtime.h>

// ---------------------------------------------------------------------------
// ConvLocalBlock: conv1d(valid, fs=5) + BN + ReLU, then per-position local
// dense layer + BN + ReLU.
//
// Key structural facts (both stages are plain GEMMs with overlapping A rows):
//  * x is [B=256, L=512, Cin=64] NWC. The conv patch x[b, t:t+5, :] is a
//    CONTIGUOUS run of 320 floats. So stage 1 is GEMM:
//      M = B*L1 = 130048, K = 320, N = 256, B-matrix = conv_w flat [320,256].
//  * y is [B, L1=508, U=256]. patches[b,l,:] = y[b, l:l+5, :] is a CONTIGUOUS
//    run of 1280 floats (U == t-stride). So stage 2 is 504 GEMMs:
//      M = 256 (batch), K = 1280, N = 256, B-matrix = local_w[l] [1280,256].
//
// Engine: fp32 SGEMM with packed fma.rn.f32x2 (sm_103a FFMA2, 2x fp32 rate).
// BM=BN=128, BK=16, 256 threads, 8x8 per-thread tile (as 8x4 f32x2 pairs).
// All tile dims divide the problem dims exactly -> no bounds checks.
// ---------------------------------------------------------------------------

#define FSZ   5
#define NB    256          // batch
#define LIN   512
#define CIN   64
#define UDIM  256
#define L1DIM 508          // LIN - FSZ + 1
#define L2DIM 504          // L1DIM - FSZ + 1
#define KCONV (FSZ * CIN)  // 320
#define KLOC  (FSZ * UDIM) // 1280
#define BNEPS 0.001f

// scratch for intermediate y: 256*508*256 floats = 133 MB (static __device__,
// allowed; runtime allocation is not)
__device__ float g_y[(size_t)NB * L1DIM * UDIM];

// ---- packed f32x2 helpers --------------------------------------------------
__device__ __forceinline__ unsigned long long pk2(float lo, float hi) {
    unsigned long long r;
    asm("mov.b64 %0, {%1, %2};" : "=l"(r) : "f"(lo), "f"(hi));
    return r;
}
__device__ __forceinline__ void upk2(unsigned long long v, float& lo, float& hi) {
    asm("mov.b64 {%0, %1}, %2;" : "=f"(lo), "=f"(hi) : "l"(v));
}
__device__ __forceinline__ unsigned long long ffma2(unsigned long long a,
                                                    unsigned long long b,
                                                    unsigned long long c) {
    unsigned long long d;
    asm("fma.rn.f32x2 %0, %1, %2, %3;" : "=l"(d) : "l"(a), "l"(b), "l"(c));
    return d;
}

// ---------------------------------------------------------------------------
// Stage 1: conv + BN1 + ReLU  ->  g_y
// grid: (N/128 = 2, M/128 = 1016), 256 threads
// ---------------------------------------------------------------------------
__global__ __launch_bounds__(256, 2)
void conv_bn_relu_kernel(const float* __restrict__ x,
                         const float* __restrict__ w,      // [320,256]
                         const float* __restrict__ cb,
                         const float* __restrict__ g1, const float* __restrict__ b1,
                         const float* __restrict__ m1, const float* __restrict__ v1)
{
    __shared__ float As[16][132];     // [k][m], padded
    __shared__ float Bs[16][128];     // [k][n]
    __shared__ const float* rowp[128];

    const int tid = threadIdx.x;
    const int n0  = blockIdx.x * 128;
    const int bm  = blockIdx.y;       // 0..1015

    if (tid < 128) {
        unsigned gm = bm * 128 + tid;
        unsigned b  = gm / L1DIM;
        unsigned t  = gm - b * L1DIM;
        rowp[tid] = x + ((size_t)b * LIN + t) * CIN;   // 320 contiguous floats
    }
    __syncthreads();

    const int tx = tid & 15, ty = tid >> 4;
    const int msub = ty * 8, nsub = tx * 8;

    unsigned long long acc[8][4] = {};

    for (int k0 = 0; k0 < KCONV; k0 += 16) {
        // load A tile: 128 rows x 16 k, as float4 along k
        #pragma unroll
        for (int it = 0; it < 2; it++) {
            int idx  = tid + it * 256;
            int arow = idx >> 2;
            int k4   = (idx & 3) * 4;
            float4 v = *(const float4*)(rowp[arow] + k0 + k4);
            As[k4 + 0][arow] = v.x;
            As[k4 + 1][arow] = v.y;
            As[k4 + 2][arow] = v.z;
            As[k4 + 3][arow] = v.w;
        }
        // load B tile: 16 k x 128 n
        #pragma unroll
        for (int it = 0; it < 2; it++) {
            int idx = tid + it * 256;
            int kr  = idx >> 5;
            int c4  = (idx & 31) * 4;
            float4 v = *(const float4*)(w + (size_t)(k0 + kr) * UDIM + n0 + c4);
            *(float4*)&Bs[kr][c4] = v;
        }
        __syncthreads();

        #pragma unroll
        for (int kk = 0; kk < 16; kk++) {
            float4 a0 = *(const float4*)&As[kk][msub];
            float4 a1 = *(const float4*)&As[kk][msub + 4];
            float4 bv0 = *(const float4*)&Bs[kk][nsub];
            float4 bv1 = *(const float4*)&Bs[kk][nsub + 4];
            unsigned long long bb[4] = { pk2(bv0.x, bv0.y), pk2(bv0.z, bv0.w),
                                         pk2(bv1.x, bv1.y), pk2(bv1.z, bv1.w) };
            float av[8] = { a0.x, a0.y, a0.z, a0.w, a1.x, a1.y, a1.z, a1.w };
            #pragma unroll
            for (int i = 0; i < 8; i++) {
                unsigned long long aa = pk2(av[i], av[i]);
                #pragma unroll
                for (int jj = 0; jj < 4; jj++)
                    acc[i][jj] = ffma2(aa, bb[jj], acc[i][jj]);
            }
        }
        __syncthreads();
    }

    // epilogue: BN1 + ReLU, write y
    float al[8], be[8];
    #pragma unroll
    for (int j = 0; j < 8; j++) {
        int n = n0 + nsub + j;
        float a_ = g1[n] * rsqrtf(v1[n] + BNEPS);
        al[j] = a_;
        be[j] = b1[n] + (cb[n] - m1[n]) * a_;
    }
    #pragma unroll
    for (int i = 0; i < 8; i++) {
        unsigned gm = bm * 128 + msub + i;
        float* orow = g_y + (size_t)gm * UDIM + n0 + nsub;
        float o[8];
        #pragma unroll
        for (int jj = 0; jj < 4; jj++) upk2(acc[i][jj], o[2*jj], o[2*jj+1]);
        float4 r0, r1;
        r0.x = fmaxf(o[0]*al[0]+be[0], 0.f); r0.y = fmaxf(o[1]*al[1]+be[1], 0.f);
        r0.z = fmaxf(o[2]*al[2]+be[2], 0.f); r0.w = fmaxf(o[3]*al[3]+be[3], 0.f);
        r1.x = fmaxf(o[4]*al[4]+be[4], 0.f); r1.y = fmaxf(o[5]*al[5]+be[5], 0.f);
        r1.z = fmaxf(o[6]*al[6]+be[6], 0.f); r1.w = fmaxf(o[7]*al[7]+be[7], 0.f);
        *(float4*)(orow)     = r0;
        *(float4*)(orow + 4) = r1;
    }
}

// ---------------------------------------------------------------------------
// Stage 2: local dense + BN2 + ReLU  ->  z
// grid: (N/128 = 2, M/128 = 2, L2 = 504), 256 threads
// ---------------------------------------------------------------------------
__global__ __launch_bounds__(256, 2)
void local_bn_relu_kernel(const float* __restrict__ lw,   // [504,1280,256]
                          const float* __restrict__ lb,   // [504,256]
                          const float* __restrict__ g2, const float* __restrict__ b2,
                          const float* __restrict__ m2, const float* __restrict__ v2,
                          float* __restrict__ z)
{
    __shared__ float As[16][132];
    __shared__ float Bs[16][128];
    __shared__ const float* rowp[128];

    const int tid = threadIdx.x;
    const int n0  = blockIdx.x * 128;
    const int mb0 = blockIdx.y * 128;   // batch tile base
    const int l   = blockIdx.z;         // 0..503

    if (tid < 128) {
        int b = mb0 + tid;
        rowp[tid] = g_y + ((size_t)b * L1DIM + l) * UDIM;  // 1280 contiguous floats
    }
    __syncthreads();

    const int tx = tid & 15, ty = tid >> 4;
    const int msub = ty * 8, nsub = tx * 8;
    const float* wl = lw + (size_t)l * KLOC * UDIM;

    unsigned long long acc[8][4] = {};

    for (int k0 = 0; k0 < KLOC; k0 += 16) {
        #pragma unroll
        for (int it = 0; it < 2; it++) {
            int idx  = tid + it * 256;
            int arow = idx >> 2;
            int k4   = (idx & 3) * 4;
            float4 v = *(const float4*)(rowp[arow] + k0 + k4);
            As[k4 + 0][arow] = v.x;
            As[k4 + 1][arow] = v.y;
            As[k4 + 2][arow] = v.z;
            As[k4 + 3][arow] = v.w;
        }
        #pragma unroll
        for (int it = 0; it < 2; it++) {
            int idx = tid + it * 256;
            int kr  = idx >> 5;
            int c4  = (idx & 31) * 4;
            float4 v = *(const float4*)(wl + (size_t)(k0 + kr) * UDIM + n0 + c4);
            *(float4*)&Bs[kr][c4] = v;
        }
        __syncthreads();

        #pragma unroll
        for (int kk = 0; kk < 16; kk++) {
            float4 a0 = *(const float4*)&As[kk][msub];
            float4 a1 = *(const float4*)&As[kk][msub + 4];
            float4 bv0 = *(const float4*)&Bs[kk][nsub];
            float4 bv1 = *(const float4*)&Bs[kk][nsub + 4];
            unsigned long long bb[4] = { pk2(bv0.x, bv0.y), pk2(bv0.z, bv0.w),
                                         pk2(bv1.x, bv1.y), pk2(bv1.z, bv1.w) };
            float av[8] = { a0.x, a0.y, a0.z, a0.w, a1.x, a1.y, a1.z, a1.w };
            #pragma unroll
            for (int i = 0; i < 8; i++) {
                unsigned long long aa = pk2(av[i], av[i]);
                #pragma unroll
                for (int jj = 0; jj < 4; jj++)
                    acc[i][jj] = ffma2(aa, bb[jj], acc[i][jj]);
            }
        }
        __syncthreads();
    }

    // epilogue: + local_b, BN2, ReLU
    float al[8], be[8];
    #pragma unroll
    for (int j = 0; j < 8; j++) {
        int n = n0 + nsub + j;
        float a_ = g2[n] * rsqrtf(v2[n] + BNEPS);
        al[j] = a_;
        be[j] = b2[n] + (lb[(size_t)l * UDIM + n] - m2[n]) * a_;
    }
    #pragma unroll
    for (int i = 0; i < 8; i++) {
        int gb = mb0 + msub + i;
        float* orow = z + ((size_t)gb * L2DIM + l) * UDIM + n0 + nsub;
        float o[8];
        #pragma unroll
        for (int jj = 0; jj < 4; jj++) upk2(acc[i][jj], o[2*jj], o[2*jj+1]);
        float4 r0, r1;
        r0.x = fmaxf(o[0]*al[0]+be[0], 0.f); r0.y = fmaxf(o[1]*al[1]+be[1], 0.f);
        r0.z = fmaxf(o[2]*al[2]+be[2], 0.f); r0.w = fmaxf(o[3]*al[3]+be[3], 0.f);
        r1.x = fmaxf(o[4]*al[4]+be[4], 0.f); r1.y = fmaxf(o[5]*al[5]+be[5], 0.f);
        r1.z = fmaxf(o[6]*al[6]+be[6], 0.f); r1.w = fmaxf(o[7]*al[7]+be[7], 0.f);
        *(float4*)(orow)     = r0;
        *(float4*)(orow + 4) = r1;
    }
}

// ---------------------------------------------------------------------------
extern "C" void kernel_launch(void* const* d_in, const int* in_sizes, int n_in,
                              void* d_out, int out_size)
{
    const float* x      = (const float*)d_in[0];
    const float* conv_w = (const float*)d_in[1];   // [5,64,256] -> flat [320,256]
    const float* conv_b = (const float*)d_in[2];
    const float* g1     = (const float*)d_in[3];
    const float* b1     = (const float*)d_in[4];
    const float* m1     = (const float*)d_in[5];
    const float* v1     = (const float*)d_in[6];
    const float* lw     = (const float*)d_in[7];   // [504,1280,256]
    const float* lb     = (const float*)d_in[8];   // [504,256]
    const float* g2     = (const float*)d_in[9];
    const float* b2     = (const float*)d_in[10];
    const float* m2     = (const float*)d_in[11];
    const float* v2     = (const float*)d_in[12];
    float* z = (float*)d_out;

    // Stage 1: M = 256*508 = 130048 = 128*1016, N = 256 = 128*2, K = 320
    dim3 grid1(2, 1016, 1);
    conv_bn_relu_kernel<<<grid1, 256>>>(x, conv_w, conv_b, g1, b1, m1, v1);

    // Stage 2: per-l GEMMs, M = 256, N = 256, K = 1280
    dim3 grid2(2, 2, L2DIM);
    local_bn_relu_kernel<<<grid2, 256>>>(lw, lb, g2, b2, m2, v2, z);
}

// round 7
// speedup vs baseline: 2.6616x; 2.6616x over previous
#include <cuda_runtime.h>
#include <cstdint>

// ---------------------------------------------------------------------------
// ConvLocalBlock via legacy mma.sync.m16n8k8 tf32 (PTX compute_103-safe; the
// harness's PTX target has no 'a' suffix so tcgen05/TMEM are unavailable).
//
// Stage 1: y = relu(bn1(x_patches @ conv_w))      M=130048 K=320  N=256
// Stage 2: z[:,l,:] = relu(bn2(y_win @ lw[l]))    per l: M=256 K=1280 N=256
// A rows are contiguous K-major runs (conv patch = 320 floats; local window
// = 1280 floats). B is [K,N] with N contiguous.
//
// CTA: 128(M)x128(N), 256 thr = 8 warps as 4x2, warp tile 32x64.
// cp.async 4-stage ring, KC=32 per stage. Padded SMEM (A stride 36 floats,
// B stride 132 floats) => all fragment LDS bank-conflict-free.
// Fragments rounded with cvt.rna.tf32.f32 (unbiased).
// ---------------------------------------------------------------------------

#define FSZ   5
#define NB    256
#define LIN   512
#define CIN   64
#define UDIM  256
#define L1DIM 508
#define L2DIM 504
#define KCONV 320
#define KLOC  1280
#define BNEPS 0.001f

#define NSTAGE  4
#define KC      32
#define ASTR    36                    // A smem row stride (floats)
#define BSTR    132                   // B smem row stride (floats)
#define A_BYTES (128 * ASTR * 4)      // 18432
#define B_BYTES (KC * BSTR * 4)       // 16896
#define STAGE_BYTES (A_BYTES + B_BYTES) // 35328 (16B-aligned)
#define SMEM_ALPHA  0                 // 128 floats
#define SMEM_BETA   512               // 128 floats
#define SMEM_STAGE0 1024
#define SMEM_TOTAL  (SMEM_STAGE0 + NSTAGE * STAGE_BYTES)  // 142336

__device__ __align__(128) float g_y[(size_t)NB * L1DIM * UDIM];

// ---- PTX helpers -----------------------------------------------------------
__device__ __forceinline__ uint32_t smem_u32(const void* p) {
    uint32_t a;
    asm("{ .reg .u64 t; cvta.to.shared.u64 t, %1; cvt.u32.u64 %0, t; }"
        : "=r"(a) : "l"(p));
    return a;
}
#define CP_ASYNC16(dst, src) \
    asm volatile("cp.async.cg.shared.global [%0], [%1], 16;" \
                 :: "r"(dst), "l"(src) : "memory")
#define CP_COMMIT() asm volatile("cp.async.commit_group;" ::: "memory")
#define CP_WAIT2()  asm volatile("cp.async.wait_group 2;" ::: "memory")

__device__ __forceinline__ uint32_t to_tf32(float f) {
    uint32_t u;
    asm("cvt.rna.tf32.f32 %0, %1;" : "=r"(u) : "f"(f));
    return u;
}
__device__ __forceinline__ void mma8(float* d, const uint32_t* a, const uint32_t* b) {
    asm volatile("mma.sync.aligned.m16n8k8.row.col.f32.tf32.tf32.f32 "
                 "{%0,%1,%2,%3}, {%4,%5,%6,%7}, {%8,%9}, {%0,%1,%2,%3};"
                 : "+f"(d[0]), "+f"(d[1]), "+f"(d[2]), "+f"(d[3])
                 : "r"(a[0]), "r"(a[1]), "r"(a[2]), "r"(a[3]),
                   "r"(b[0]), "r"(b[1]));
}

// one pipeline-stage load: A 128 rows x 32 floats (128B) + B 32 k-rows x 128 n
__device__ __forceinline__ void load_stage(uint32_t sb, const float* const* aptr,
                                           const float* bsrc0, int tid) {
    const int achunk = tid & 7;        // 16B chunk within A row
    const int bchunk = tid & 31;       // 16B chunk within B row
    #pragma unroll
    for (int p = 0; p < 4; p++) {
        int arow = (tid >> 3) + p * 32;
        uint32_t adst = sb + (uint32_t)(arow * ASTR + achunk * 4) * 4;
        CP_ASYNC16(adst, aptr[p] + achunk * 4);
    }
    const uint32_t sbB = sb + A_BYTES;
    #pragma unroll
    for (int p = 0; p < 4; p++) {
        int brow = (tid >> 5) + p * 8;
        uint32_t bdst = sbB + (uint32_t)(brow * BSTR + bchunk * 4) * 4;
        CP_ASYNC16(bdst, bsrc0 + (size_t)brow * UDIM + bchunk * 4);
    }
}

// ---------------------------------------------------------------------------
// MODE 0: conv stage.  grid (1016 m-tiles, 2 n-tiles).   A=x, out=g_y
// MODE 1: local stage. grid (2 m, 2 n, 504 l).           A=g_y, out=z
// ---------------------------------------------------------------------------
template <int MODE>
__global__ void __launch_bounds__(256, 1)
gemm_mma(const float* __restrict__ Ain, const float* __restrict__ Bmat0,
         const float* __restrict__ bias, const float* __restrict__ gg,
         const float* __restrict__ bbn, const float* __restrict__ mmn,
         const float* __restrict__ vvn, float* __restrict__ outp)
{
    extern __shared__ char smem[];
    const uint32_t sb0 = smem_u32(smem) + SMEM_STAGE0;
    const int tid  = threadIdx.x;
    const int wid  = tid >> 5;
    const int lane = tid & 31;
    const int wm   = wid & 3;          // warp m index (0..3)
    const int wn   = wid >> 2;         // warp n index (0..1)
    const int g    = lane >> 2;        // group id 0..7
    const int tg   = lane & 3;         // thread-in-group

    const int S   = MODE ? (KLOC / KC) : (KCONV / KC);
    const int l   = MODE ? blockIdx.z : 0;
    const int mb0 = blockIdx.x * 128;
    const int n0  = blockIdx.y * 128;

    const float* Bmat = MODE ? (Bmat0 + (size_t)l * KLOC * UDIM) : Bmat0;
    float* out = MODE ? outp : g_y;

    // BN alpha/beta for this 128-col n-tile
    if (tid < 128) {
        int n = n0 + tid;
        float a_ = gg[n] * rsqrtf(vvn[n] + BNEPS);
        float bi = MODE ? bias[(size_t)l * UDIM + n] : bias[n];
        ((float*)(smem + SMEM_ALPHA))[tid] = a_;
        ((float*)(smem + SMEM_BETA))[tid]  = bbn[n] + (bi - mmn[n]) * a_;
    }

    // per-thread A row pointers for the 4 load passes
    const float* aptr[4];
    #pragma unroll
    for (int p = 0; p < 4; p++) {
        int r = (tid >> 3) + p * 32;
        if (MODE) {
            aptr[p] = g_y + ((size_t)(mb0 + r) * L1DIM + l) * UDIM;
        } else {
            unsigned gm = mb0 + r;
            unsigned b  = gm / L1DIM;
            unsigned t  = gm - b * L1DIM;
            aptr[p] = Ain + ((size_t)b * LIN + t) * CIN;
        }
    }

    // pipeline prologue: stages 0..2
    #pragma unroll
    for (int p = 0; p < NSTAGE - 1; p++) {
        load_stage(sb0 + p * STAGE_BYTES, aptr, Bmat + (size_t)(p * KC) * UDIM + n0, tid);
        #pragma unroll
        for (int i = 0; i < 4; i++) aptr[i] += KC;
        CP_COMMIT();
    }

    float acc[2][8][4] = {};

    // fragment base offsets (floats) within a stage
    const int aoff = (wm * 32 + g) * ASTR + tg;
    const int boff = tg * BSTR + wn * 64 + g;

    for (int s = 0; s < S; s++) {
        int pn = s + NSTAGE - 1;
        if (pn < S) {
            load_stage(sb0 + (pn & (NSTAGE - 1)) * STAGE_BYTES, aptr,
                       Bmat + (size_t)(pn * KC) * UDIM + n0, tid);
            #pragma unroll
            for (int i = 0; i < 4; i++) aptr[i] += KC;
        }
        CP_COMMIT();
        CP_WAIT2();
        __syncthreads();

        const float* As = (const float*)(smem + SMEM_STAGE0 +
                                         (s & (NSTAGE - 1)) * STAGE_BYTES);
        const float* Bs = As + 128 * ASTR;
        const float* aB = As + aoff;
        const float* bB = Bs + boff;

        #pragma unroll
        for (int k8 = 0; k8 < KC / 8; k8++) {
            const int kk = k8 * 8;
            uint32_t af[2][4];
            #pragma unroll
            for (int mf = 0; mf < 2; mf++) {
                const float* p0 = aB + mf * 16 * ASTR + kk;
                af[mf][0] = to_tf32(p0[0]);
                af[mf][1] = to_tf32(p0[8 * ASTR]);
                af[mf][2] = to_tf32(p0[4]);
                af[mf][3] = to_tf32(p0[8 * ASTR + 4]);
            }
            uint32_t bf[8][2];
            #pragma unroll
            for (int jf = 0; jf < 8; jf++) {
                const float* p0 = bB + kk * BSTR + jf * 8;
                bf[jf][0] = to_tf32(p0[0]);
                bf[jf][1] = to_tf32(p0[4 * BSTR]);
            }
            #pragma unroll
            for (int mf = 0; mf < 2; mf++)
                #pragma unroll
                for (int jf = 0; jf < 8; jf++)
                    mma8(acc[mf][jf], af[mf], bf[jf]);
        }
        __syncthreads();
    }

    // ---- epilogue: BN + ReLU, write out ----
    const float* al = (const float*)(smem + SMEM_ALPHA);
    const float* be = (const float*)(smem + SMEM_BETA);
    #pragma unroll
    for (int mf = 0; mf < 2; mf++) {
        int r0 = mb0 + wm * 32 + mf * 16 + g;   // and r0+8
        float* orow0;
        float* orow1;
        if (MODE) {
            orow0 = out + ((size_t)r0 * L2DIM + l) * UDIM;
            orow1 = out + ((size_t)(r0 + 8) * L2DIM + l) * UDIM;
        } else {
            orow0 = out + (size_t)r0 * UDIM;
            orow1 = out + (size_t)(r0 + 8) * UDIM;
        }
        #pragma unroll
        for (int jf = 0; jf < 8; jf++) {
            int cl = wn * 64 + jf * 8 + 2 * tg;   // local col (0..127)
            float a0 = al[cl], a1 = al[cl + 1];
            float e0 = be[cl], e1 = be[cl + 1];
            float2 v0, v1;
            v0.x = fmaxf(acc[mf][jf][0] * a0 + e0, 0.f);
            v0.y = fmaxf(acc[mf][jf][1] * a1 + e1, 0.f);
            v1.x = fmaxf(acc[mf][jf][2] * a0 + e0, 0.f);
            v1.y = fmaxf(acc[mf][jf][3] * a1 + e1, 0.f);
            *(float2*)(orow0 + n0 + cl) = v0;
            *(float2*)(orow1 + n0 + cl) = v1;
        }
    }
}

// ---------------------------------------------------------------------------
extern "C" void kernel_launch(void* const* d_in, const int* in_sizes, int n_in,
                              void* d_out, int out_size)
{
    const float* x      = (const float*)d_in[0];
    const float* conv_w = (const float*)d_in[1];
    const float* conv_b = (const float*)d_in[2];
    const float* g1     = (const float*)d_in[3];
    const float* b1     = (const float*)d_in[4];
    const float* m1     = (const float*)d_in[5];
    const float* v1     = (const float*)d_in[6];
    const float* lw     = (const float*)d_in[7];
    const float* lb     = (const float*)d_in[8];
    const float* g2     = (const float*)d_in[9];
    const float* b2     = (const float*)d_in[10];
    const float* m2     = (const float*)d_in[11];
    const float* v2     = (const float*)d_in[12];
    float* z = (float*)d_out;

    static bool attr_set = false;
    if (!attr_set) {
        cudaFuncSetAttribute(gemm_mma<0>,
            cudaFuncAttributeMaxDynamicSharedMemorySize, SMEM_TOTAL);
        cudaFuncSetAttribute(gemm_mma<1>,
            cudaFuncAttributeMaxDynamicSharedMemorySize, SMEM_TOTAL);
        attr_set = true;
    }

    // Stage 1: M=130048 (1016 tiles), N=256 (2 tiles), K=320
    gemm_mma<0><<<dim3(1016, 2, 1), 256, SMEM_TOTAL>>>(
        x, conv_w, conv_b, g1, b1, m1, v1, nullptr);

    // Stage 2: per-l GEMMs, M=256 (2), N=256 (2), K=1280, l=504
    gemm_mma<1><<<dim3(2, 2, L2DIM), 256, SMEM_TOTAL>>>(
        nullptr, lw, lb, g2, b2, m2, v2, z);
}

// round 8
// speedup vs baseline: 3.0786x; 1.1567x over previous
#include <cuda_runtime.h>
#include <cstdint>

// ---------------------------------------------------------------------------
// ConvLocalBlock via legacy mma.sync.m16n8k8 tf32 (PTX compute_103-safe; the
// harness's PTX target has no 'a' suffix so tcgen05/TMEM are unavailable).
//
// Stage 1: y = relu(bn1(x_patches @ conv_w))      M=130048 K=320  N=256
// Stage 2: z[:,l,:] = relu(bn2(y_win @ lw[l]))    per l: M=256 K=1280 N=256
// A rows are contiguous K-major runs (conv patch = 320 floats; local window
// = 1280 floats). B is [K,N] with N contiguous.
//
// CTA: 128(M)x128(N), 256 thr = 8 warps as 4x2, warp tile 32x64.
// R8 change vs R7: 3-stage cp.async ring (104.5 KB SMEM) + launch_bounds
// (256,2) => 2 CTAs/SM (16 warps) to hide LDS/cvt/barrier latency that held
// issue at 35% and tensor at 41%.
// Padded SMEM (A stride 36, B stride 132 floats) => conflict-free fragment LDS.
// Fragments rounded with cvt.rna.tf32.f32 (unbiased).
// ---------------------------------------------------------------------------

#define FSZ   5
#define NB    256
#define LIN   512
#define CIN   64
#define UDIM  256
#define L1DIM 508
#define L2DIM 504
#define KCONV 320
#define KLOC  1280
#define BNEPS 0.001f

#define NSTAGE  3
#define KC      32
#define ASTR    36                    // A smem row stride (floats)
#define BSTR    132                   // B smem row stride (floats)
#define A_BYTES (128 * ASTR * 4)      // 18432
#define B_BYTES (KC * BSTR * 4)       // 16896
#define STAGE_BYTES (A_BYTES + B_BYTES) // 35328 (16B-aligned)
#define SMEM_ALPHA  0                 // 128 floats
#define SMEM_BETA   512               // 128 floats
#define SMEM_STAGE0 1024
#define SMEM_TOTAL  (SMEM_STAGE0 + NSTAGE * STAGE_BYTES)  // 107008 (104.5 KB)

__device__ __align__(128) float g_y[(size_t)NB * L1DIM * UDIM];

// ---- PTX helpers -----------------------------------------------------------
__device__ __forceinline__ uint32_t smem_u32(const void* p) {
    uint32_t a;
    asm("{ .reg .u64 t; cvta.to.shared.u64 t, %1; cvt.u32.u64 %0, t; }"
        : "=r"(a) : "l"(p));
    return a;
}
#define CP_ASYNC16(dst, src) \
    asm volatile("cp.async.cg.shared.global [%0], [%1], 16;" \
                 :: "r"(dst), "l"(src) : "memory")
#define CP_COMMIT() asm volatile("cp.async.commit_group;" ::: "memory")
// stage s resident when all but 2 newest groups have drained (see loop math)
#define CP_WAIT2()  asm volatile("cp.async.wait_group 2;" ::: "memory")

__device__ __forceinline__ uint32_t to_tf32(float f) {
    uint32_t u;
    asm("cvt.rna.tf32.f32 %0, %1;" : "=r"(u) : "f"(f));
    return u;
}
__device__ __forceinline__ void mma8(float* d, const uint32_t* a, const uint32_t* b) {
    asm volatile("mma.sync.aligned.m16n8k8.row.col.f32.tf32.tf32.f32 "
                 "{%0,%1,%2,%3}, {%4,%5,%6,%7}, {%8,%9}, {%0,%1,%2,%3};"
                 : "+f"(d[0]), "+f"(d[1]), "+f"(d[2]), "+f"(d[3])
                 : "r"(a[0]), "r"(a[1]), "r"(a[2]), "r"(a[3]),
                   "r"(b[0]), "r"(b[1]));
}

// one pipeline-stage load: A 128 rows x 32 floats (128B) + B 32 k-rows x 128 n
__device__ __forceinline__ void load_stage(uint32_t sb, const float* const* aptr,
                                           const float* bsrc0, int tid) {
    const int achunk = tid & 7;        // 16B chunk within A row
    const int bchunk = tid & 31;       // 16B chunk within B row
    #pragma unroll
    for (int p = 0; p < 4; p++) {
        int arow = (tid >> 3) + p * 32;
        uint32_t adst = sb + (uint32_t)(arow * ASTR + achunk * 4) * 4;
        CP_ASYNC16(adst, aptr[p] + achunk * 4);
    }
    const uint32_t sbB = sb + A_BYTES;
    #pragma unroll
    for (int p = 0; p < 4; p++) {
        int brow = (tid >> 5) + p * 8;
        uint32_t bdst = sbB + (uint32_t)(brow * BSTR + bchunk * 4) * 4;
        CP_ASYNC16(bdst, bsrc0 + (size_t)brow * UDIM + bchunk * 4);
    }
}

// ---------------------------------------------------------------------------
// MODE 0: conv stage.  grid (1016 m-tiles, 2 n-tiles).   A=x, out=g_y
// MODE 1: local stage. grid (2 m, 2 n, 504 l).           A=g_y, out=z
// ---------------------------------------------------------------------------
template <int MODE>
__global__ void __launch_bounds__(256, 2)
gemm_mma(const float* __restrict__ Ain, const float* __restrict__ Bmat0,
         const float* __restrict__ bias, const float* __restrict__ gg,
         const float* __restrict__ bbn, const float* __restrict__ mmn,
         const float* __restrict__ vvn, float* __restrict__ outp)
{
    extern __shared__ char smem[];
    const uint32_t sb0 = smem_u32(smem) + SMEM_STAGE0;
    const int tid  = threadIdx.x;
    const int wid  = tid >> 5;
    const int lane = tid & 31;
    const int wm   = wid & 3;          // warp m index (0..3)
    const int wn   = wid >> 2;         // warp n index (0..1)
    const int g    = lane >> 2;        // group id 0..7
    const int tg   = lane & 3;         // thread-in-group

    const int S   = MODE ? (KLOC / KC) : (KCONV / KC);
    const int l   = MODE ? blockIdx.z : 0;
    const int mb0 = blockIdx.x * 128;
    const int n0  = blockIdx.y * 128;

    const float* Bmat = MODE ? (Bmat0 + (size_t)l * KLOC * UDIM) : Bmat0;
    float* out = MODE ? outp : g_y;

    // BN alpha/beta for this 128-col n-tile
    if (tid < 128) {
        int n = n0 + tid;
        float a_ = gg[n] * rsqrtf(vvn[n] + BNEPS);
        float bi = MODE ? bias[(size_t)l * UDIM + n] : bias[n];
        ((float*)(smem + SMEM_ALPHA))[tid] = a_;
        ((float*)(smem + SMEM_BETA))[tid]  = bbn[n] + (bi - mmn[n]) * a_;
    }

    // per-thread A row pointers for the 4 load passes
    const float* aptr[4];
    #pragma unroll
    for (int p = 0; p < 4; p++) {
        int r = (tid >> 3) + p * 32;
        if (MODE) {
            aptr[p] = g_y + ((size_t)(mb0 + r) * L1DIM + l) * UDIM;
        } else {
            unsigned gm = mb0 + r;
            unsigned b  = gm / L1DIM;
            unsigned t  = gm - b * L1DIM;
            aptr[p] = Ain + ((size_t)b * LIN + t) * CIN;
        }
    }

    // pipeline prologue: stages 0..NSTAGE-2
    #pragma unroll
    for (int p = 0; p < NSTAGE - 1; p++) {
        load_stage(sb0 + p * STAGE_BYTES, aptr, Bmat + (size_t)(p * KC) * UDIM + n0, tid);
        #pragma unroll
        for (int i = 0; i < 4; i++) aptr[i] += KC;
        CP_COMMIT();
    }

    float acc[2][8][4] = {};

    // fragment base offsets (floats) within a stage
    const int aoff = (wm * 32 + g) * ASTR + tg;
    const int boff = tg * BSTR + wn * 64 + g;

    // loop math: at iter s, commits issued = (NSTAGE-1) + (s+1) = s+NSTAGE.
    // Stage s needs groups 0..s complete -> outstanding allowed = NSTAGE-1 = 2.
    for (int s = 0; s < S; s++) {
        int pn = s + NSTAGE - 1;
        if (pn < S) {
            load_stage(sb0 + (pn % NSTAGE) * STAGE_BYTES, aptr,
                       Bmat + (size_t)(pn * KC) * UDIM + n0, tid);
            #pragma unroll
            for (int i = 0; i < 4; i++) aptr[i] += KC;
        }
        CP_COMMIT();          // uniform one group per iteration (may be empty)
        CP_WAIT2();
        __syncthreads();

        const float* As = (const float*)(smem + SMEM_STAGE0 +
                                         (s % NSTAGE) * STAGE_BYTES);
        const float* Bs = As + 128 * ASTR;
        const float* aB = As + aoff;
        const float* bB = Bs + boff;

        #pragma unroll
        for (int k8 = 0; k8 < KC / 8; k8++) {
            const int kk = k8 * 8;
            uint32_t af[2][4];
            #pragma unroll
            for (int mf = 0; mf < 2; mf++) {
                const float* p0 = aB + mf * 16 * ASTR + kk;
                af[mf][0] = to_tf32(p0[0]);
                af[mf][1] = to_tf32(p0[8 * ASTR]);
                af[mf][2] = to_tf32(p0[4]);
                af[mf][3] = to_tf32(p0[8 * ASTR + 4]);
            }
            uint32_t bf[8][2];
            #pragma unroll
            for (int jf = 0; jf < 8; jf++) {
                const float* p0 = bB + kk * BSTR + jf * 8;
                bf[jf][0] = to_tf32(p0[0]);
                bf[jf][1] = to_tf32(p0[4 * BSTR]);
            }
            #pragma unroll
            for (int mf = 0; mf < 2; mf++)
                #pragma unroll
                for (int jf = 0; jf < 8; jf++)
                    mma8(acc[mf][jf], af[mf], bf[jf]);
        }
        __syncthreads();
    }

    // ---- epilogue: BN + ReLU, write out ----
    const float* al = (const float*)(smem + SMEM_ALPHA);
    const float* be = (const float*)(smem + SMEM_BETA);
    #pragma unroll
    for (int mf = 0; mf < 2; mf++) {
        int r0 = mb0 + wm * 32 + mf * 16 + g;   // and r0+8
        float* orow0;
        float* orow1;
        if (MODE) {
            orow0 = out + ((size_t)r0 * L2DIM + l) * UDIM;
            orow1 = out + ((size_t)(r0 + 8) * L2DIM + l) * UDIM;
        } else {
            orow0 = out + (size_t)r0 * UDIM;
            orow1 = out + (size_t)(r0 + 8) * UDIM;
        }
        #pragma unroll
        for (int jf = 0; jf < 8; jf++) {
            int cl = wn * 64 + jf * 8 + 2 * tg;   // local col (0..127)
            float a0 = al[cl], a1 = al[cl + 1];
            float e0 = be[cl], e1 = be[cl + 1];
            float2 v0, v1;
            v0.x = fmaxf(acc[mf][jf][0] * a0 + e0, 0.f);
            v0.y = fmaxf(acc[mf][jf][1] * a1 + e1, 0.f);
            v1.x = fmaxf(acc[mf][jf][2] * a0 + e0, 0.f);
            v1.y = fmaxf(acc[mf][jf][3] * a1 + e1, 0.f);
            *(float2*)(orow0 + n0 + cl) = v0;
            *(float2*)(orow1 + n0 + cl) = v1;
        }
    }
}

// ---------------------------------------------------------------------------
extern "C" void kernel_launch(void* const* d_in, const int* in_sizes, int n_in,
                              void* d_out, int out_size)
{
    const float* x      = (const float*)d_in[0];
    const float* conv_w = (const float*)d_in[1];
    const float* conv_b = (const float*)d_in[2];
    const float* g1     = (const float*)d_in[3];
    const float* b1     = (const float*)d_in[4];
    const float* m1     = (const float*)d_in[5];
    const float* v1     = (const float*)d_in[6];
    const float* lw     = (const float*)d_in[7];
    const float* lb     = (const float*)d_in[8];
    const float* g2     = (const float*)d_in[9];
    const float* b2     = (const float*)d_in[10];
    const float* m2     = (const float*)d_in[11];
    const float* v2     = (const float*)d_in[12];
    float* z = (float*)d_out;

    static bool attr_set = false;
    if (!attr_set) {
        cudaFuncSetAttribute(gemm_mma<0>,
            cudaFuncAttributeMaxDynamicSharedMemorySize, SMEM_TOTAL);
        cudaFuncSetAttribute(gemm_mma<1>,
            cudaFuncAttributeMaxDynamicSharedMemorySize, SMEM_TOTAL);
        // allow 2 x 104.5 KB CTAs to co-reside (228 KB carveout)
        cudaFuncSetAttribute(gemm_mma<0>,
            cudaFuncAttributePreferredSharedMemoryCarveout, 100);
        cudaFuncSetAttribute(gemm_mma<1>,
            cudaFuncAttributePreferredSharedMemoryCarveout, 100);
        attr_set = true;
    }

    // Stage 1: M=130048 (1016 tiles), N=256 (2 tiles), K=320
    gemm_mma<0><<<dim3(1016, 2, 1), 256, SMEM_TOTAL>>>(
        x, conv_w, conv_b, g1, b1, m1, v1, nullptr);

    // Stage 2: per-l GEMMs, M=256 (2), N=256 (2), K=1280, l=504
    gemm_mma<1><<<dim3(2, 2, L2DIM), 256, SMEM_TOTAL>>>(
        nullptr, lw, lb, g2, b2, m2, v2, z);
}

// round 10
// speedup vs baseline: 3.1241x; 1.0148x over previous
#include <cuda_runtime.h>
#include <cstdint>

// ---------------------------------------------------------------------------
// ConvLocalBlock via legacy mma.sync.m16n8k8 tf32 (PTX compute_103-safe; the
// harness's PTX target has no 'a' suffix so tcgen05/TMEM are unavailable).
//
// Stage 1: y = relu(bn1(x_patches @ conv_w))      M=130048 K=320  N=256
// Stage 2: z[:,l,:] = relu(bn2(y_win @ lw[l]))    per l: M=256 K=1280 N=256
//
// R9 changes vs R8 (mix was 24 LDS + 24 cvt + 16 HMMA per k8 -> tensor capped
// at 47%):
//  * cvt.rna.tf32 removed entirely: raw fp32 bits fed to tf32 MMA (HW RZ-
//    truncates low 13 bits). The coherent truncation bias (~7.04e-4 on each
//    product) is cancelled analytically by scaling the GEMM term by
//    TCORR = 1.0007045 (folded into BN alpha, both stages).
//  * A fragments via ldmatrix.m8n8.x4.b16 (b16 tiles over f32 = fragment
//    quadrants): 8 LDS -> 2 LDSM per k8.
// New mix: 2 LDSM + 16 LDS + 16 HMMA = 34 instr/k8.
//
// CTA: 128x128, 8 warps (4x2), warp tile 32x64, 3-stage cp.async ring,
// 2 CTAs/SM. Padded SMEM (A stride 36, B stride 132 floats): conflict-free.
// ---------------------------------------------------------------------------

#define FSZ   5
#define NB    256
#define LIN   512
#define CIN   64
#define UDIM  256
#define L1DIM 508
#define L2DIM 504
#define KCONV 320
#define KLOC  1280
#define BNEPS 0.001f
#define TCORR 1.0007045f              // cancels tf32 RZ-truncation product bias

#define NSTAGE  3
#define KC      32
#define ASTR    36                    // A smem row stride (floats)
#define BSTR    132                   // B smem row stride (floats)
#define A_BYTES (128 * ASTR * 4)      // 18432
#define B_BYTES (KC * BSTR * 4)       // 16896
#define STAGE_BYTES (A_BYTES + B_BYTES) // 35328
#define SMEM_ALPHA  0
#define SMEM_BETA   512
#define SMEM_STAGE0 1024
#define SMEM_TOTAL  (SMEM_STAGE0 + NSTAGE * STAGE_BYTES)  // 107008

__device__ __align__(128) float g_y[(size_t)NB * L1DIM * UDIM];

// ---- PTX helpers -----------------------------------------------------------
__device__ __forceinline__ uint32_t smem_u32(const void* p) {
    uint32_t a;
    asm("{ .reg .u64 t; cvta.to.shared.u64 t, %1; cvt.u32.u64 %0, t; }"
        : "=r"(a) : "l"(p));
    return a;
}
#define CP_ASYNC16(dst, src) \
    asm volatile("cp.async.cg.shared.global [%0], [%1], 16;" \
                 :: "r"(dst), "l"(src) : "memory")
#define CP_COMMIT() asm volatile("cp.async.commit_group;" ::: "memory")
#define CP_WAIT2()  asm volatile("cp.async.wait_group 2;" ::: "memory")

__device__ __forceinline__ void ldsm_x4(uint32_t* r, uint32_t addr) {
    asm volatile("ldmatrix.sync.aligned.m8n8.x4.shared.b16 {%0,%1,%2,%3}, [%4];"
                 : "=r"(r[0]), "=r"(r[1]), "=r"(r[2]), "=r"(r[3]) : "r"(addr));
}
__device__ __forceinline__ void mma8(float* d, const uint32_t* a, const uint32_t* b) {
    asm volatile("mma.sync.aligned.m16n8k8.row.col.f32.tf32.tf32.f32 "
                 "{%0,%1,%2,%3}, {%4,%5,%6,%7}, {%8,%9}, {%0,%1,%2,%3};"
                 : "+f"(d[0]), "+f"(d[1]), "+f"(d[2]), "+f"(d[3])
                 : "r"(a[0]), "r"(a[1]), "r"(a[2]), "r"(a[3]),
                   "r"(b[0]), "r"(b[1]));
}

// one pipeline-stage load: A 128 rows x 32 floats + B 32 k-rows x 128 n
__device__ __forceinline__ void load_stage(uint32_t sb, const float* const* aptr,
                                           const float* bsrc0, int tid) {
    const int achunk = tid & 7;
    const int bchunk = tid & 31;
    #pragma unroll
    for (int p = 0; p < 4; p++) {
        int arow = (tid >> 3) + p * 32;
        uint32_t adst = sb + (uint32_t)(arow * ASTR + achunk * 4) * 4;
        CP_ASYNC16(adst, aptr[p] + achunk * 4);
    }
    const uint32_t sbB = sb + A_BYTES;
    #pragma unroll
    for (int p = 0; p < 4; p++) {
        int brow = (tid >> 5) + p * 8;
        uint32_t bdst = sbB + (uint32_t)(brow * BSTR + bchunk * 4) * 4;
        CP_ASYNC16(bdst, bsrc0 + (size_t)brow * UDIM + bchunk * 4);
    }
}

// ---------------------------------------------------------------------------
// MODE 0: conv stage.  grid (1016 m-tiles, 2 n-tiles).   A=x, out=g_y
// MODE 1: local stage. grid (2 m, 2 n, 504 l).           A=g_y, out=z
// ---------------------------------------------------------------------------
template <int MODE>
__global__ void __launch_bounds__(256, 2)
gemm_mma(const float* __restrict__ Ain, const float* __restrict__ Bmat0,
         const float* __restrict__ bias, const float* __restrict__ gg,
         const float* __restrict__ bbn, const float* __restrict__ mmn,
         const float* __restrict__ vvn, float* __restrict__ outp)
{
    extern __shared__ char smem[];
    const uint32_t sbase = smem_u32(smem);
    const uint32_t sb0 = sbase + SMEM_STAGE0;
    const int tid  = threadIdx.x;
    const int wid  = tid >> 5;
    const int lane = tid & 31;
    const int wm   = wid & 3;
    const int wn   = wid >> 2;
    const int g    = lane >> 2;
    const int tg   = lane & 3;

    const int S   = MODE ? (KLOC / KC) : (KCONV / KC);
    const int l   = MODE ? blockIdx.z : 0;
    const int mb0 = blockIdx.x * 128;
    const int n0  = blockIdx.y * 128;

    const float* Bmat = MODE ? (Bmat0 + (size_t)l * KLOC * UDIM) : Bmat0;
    float* out = MODE ? outp : g_y;

    // BN alpha/beta (alpha carries the tf32-truncation bias correction)
    if (tid < 128) {
        int n = n0 + tid;
        float a_ = gg[n] * rsqrtf(vvn[n] + BNEPS);
        float bi = MODE ? bias[(size_t)l * UDIM + n] : bias[n];
        ((float*)(smem + SMEM_ALPHA))[tid] = a_ * TCORR;
        ((float*)(smem + SMEM_BETA))[tid]  = bbn[n] + (bi - mmn[n]) * a_;
    }

    // per-thread A row pointers for the 4 load passes
    const float* aptr[4];
    #pragma unroll
    for (int p = 0; p < 4; p++) {
        int r = (tid >> 3) + p * 32;
        if (MODE) {
            aptr[p] = g_y + ((size_t)(mb0 + r) * L1DIM + l) * UDIM;
        } else {
            unsigned gm = mb0 + r;
            unsigned b  = gm / L1DIM;
            unsigned t  = gm - b * L1DIM;
            aptr[p] = Ain + ((size_t)b * LIN + t) * CIN;
        }
    }

    // pipeline prologue
    #pragma unroll
    for (int p = 0; p < NSTAGE - 1; p++) {
        load_stage(sb0 + p * STAGE_BYTES, aptr, Bmat + (size_t)(p * KC) * UDIM + n0, tid);
        #pragma unroll
        for (int i = 0; i < 4; i++) aptr[i] += KC;
        CP_COMMIT();
    }

    float acc[2][8][4] = {};

    // ldmatrix lane->tile-row mapping for A fragments:
    //  tiles (m0-7,k0-3),(m8-15,k0-3),(m0-7,k4-7),(m8-15,k4-7) -> a0..a3
    const int trow = (lane & 7) + ((lane >> 3) & 1) * 8;
    const int tk   = (lane >> 4) * 4;
    // float offsets within a stage for the two mf fragments
    const int a_lm_off0 = (wm * 32 + 0  + trow) * ASTR + tk;
    const int a_lm_off1 = (wm * 32 + 16 + trow) * ASTR + tk;
    // scalar-B fragment base offset (floats)
    const int boff = tg * BSTR + wn * 64 + g;

    for (int s = 0; s < S; s++) {
        int pn = s + NSTAGE - 1;
        if (pn < S) {
            load_stage(sb0 + (pn % NSTAGE) * STAGE_BYTES, aptr,
                       Bmat + (size_t)(pn * KC) * UDIM + n0, tid);
            #pragma unroll
            for (int i = 0; i < 4; i++) aptr[i] += KC;
        }
        CP_COMMIT();
        CP_WAIT2();
        __syncthreads();

        const uint32_t stg = sb0 + (s % NSTAGE) * STAGE_BYTES;
        const uint32_t aAddr0 = stg + (uint32_t)a_lm_off0 * 4;
        const uint32_t aAddr1 = stg + (uint32_t)a_lm_off1 * 4;
        const uint32_t* bB = (const uint32_t*)(smem + SMEM_STAGE0 +
                                               (s % NSTAGE) * STAGE_BYTES +
                                               A_BYTES) + boff;

        #pragma unroll
        for (int k8 = 0; k8 < KC / 8; k8++) {
            const int kk = k8 * 8;
            uint32_t af[2][4];
            ldsm_x4(af[0], aAddr0 + kk * 4);
            ldsm_x4(af[1], aAddr1 + kk * 4);
            uint32_t bf[8][2];
            #pragma unroll
            for (int jf = 0; jf < 8; jf++) {
                const uint32_t* p0 = bB + kk * BSTR + jf * 8;
                bf[jf][0] = p0[0];
                bf[jf][1] = p0[4 * BSTR];
            }
            #pragma unroll
            for (int mf = 0; mf < 2; mf++)
                #pragma unroll
                for (int jf = 0; jf < 8; jf++)
                    mma8(acc[mf][jf], af[mf], bf[jf]);
        }
        __syncthreads();
    }

    // ---- epilogue: BN + ReLU, write out ----
    const float* al = (const float*)(smem + SMEM_ALPHA);
    const float* be = (const float*)(smem + SMEM_BETA);
    #pragma unroll
    for (int mf = 0; mf < 2; mf++) {
        int r0 = mb0 + wm * 32 + mf * 16 + g;   // and r0+8
        float* orow0;
        float* orow1;
        if (MODE) {
            orow0 = out + ((size_t)r0 * L2DIM + l) * UDIM;
            orow1 = out + ((size_t)(r0 + 8) * L2DIM + l) * UDIM;
        } else {
            orow0 = out + (size_t)r0 * UDIM;
            orow1 = out + (size_t)(r0 + 8) * UDIM;
        }
        #pragma unroll
        for (int jf = 0; jf < 8; jf++) {
            int cl = wn * 64 + jf * 8 + 2 * tg;
            float a0 = al[cl], a1 = al[cl + 1];
            float e0 = be[cl], e1 = be[cl + 1];
            float2 v0, v1;
            v0.x = fmaxf(acc[mf][jf][0] * a0 + e0, 0.f);
            v0.y = fmaxf(acc[mf][jf][1] * a1 + e1, 0.f);
            v1.x = fmaxf(acc[mf][jf][2] * a0 + e0, 0.f);
            v1.y = fmaxf(acc[mf][jf][3] * a1 + e1, 0.f);
            *(float2*)(orow0 + n0 + cl) = v0;
            *(float2*)(orow1 + n0 + cl) = v1;
        }
    }
}

// ---------------------------------------------------------------------------
extern "C" void kernel_launch(void* const* d_in, const int* in_sizes, int n_in,
                              void* d_out, int out_size)
{
    const float* x      = (const float*)d_in[0];
    const float* conv_w = (const float*)d_in[1];
    const float* conv_b = (const float*)d_in[2];
    const float* g1     = (const float*)d_in[3];
    const float* b1     = (const float*)d_in[4];
    const float* m1     = (const float*)d_in[5];
    const float* v1     = (const float*)d_in[6];
    const float* lw     = (const float*)d_in[7];
    const float* lb     = (const float*)d_in[8];
    const float* g2     = (const float*)d_in[9];
    const float* b2     = (const float*)d_in[10];
    const float* m2     = (const float*)d_in[11];
    const float* v2     = (const float*)d_in[12];
    float* z = (float*)d_out;

    static bool attr_set = false;
    if (!attr_set) {
        cudaFuncSetAttribute(gemm_mma<0>,
            cudaFuncAttributeMaxDynamicSharedMemorySize, SMEM_TOTAL);
        cudaFuncSetAttribute(gemm_mma<1>,
            cudaFuncAttributeMaxDynamicSharedMemorySize, SMEM_TOTAL);
        cudaFuncSetAttribute(gemm_mma<0>,
            cudaFuncAttributePreferredSharedMemoryCarveout, 100);
        cudaFuncSetAttribute(gemm_mma<1>,
            cudaFuncAttributePreferredSharedMemoryCarveout, 100);
        attr_set = true;
    }

    // Stage 1: M=130048 (1016 tiles), N=256 (2 tiles), K=320
    gemm_mma<0><<<dim3(1016, 2, 1), 256, SMEM_TOTAL>>>(
        x, conv_w, conv_b, g1, b1, m1, v1, nullptr);

    // Stage 2: per-l GEMMs, M=256 (2), N=256 (2), K=1280, l=504
    gemm_mma<1><<<dim3(2, 2, L2DIM), 256, SMEM_TOTAL>>>(
        nullptr, lw, lb, g2, b2, m2, v2, z);
}

// round 11
// speedup vs baseline: 3.7409x; 1.1974x over previous
#include <cuda_runtime.h>
#include <cstdint>

// ---------------------------------------------------------------------------
// ConvLocalBlock via legacy mma.sync.m16n8k8 tf32 (PTX compute_103-safe; the
// harness's PTX target has no 'a' suffix so tcgen05/TMEM are unavailable).
//
// Stage 1: y = relu(bn1(x_patches @ conv_w))      M=130048 K=320  N=256
// Stage 2: z[:,l,:] = relu(bn2(y_win @ lw[l]))    per l: M=256 K=1280 N=256
//
// R10 changes vs R9 (tensor pinned at 48% by the SMEM crossbar, not issue):
//  * BSTR 132 -> 136 (136 mod 32 == 8): B fragment LDS lanes now map to banks
//    (8*tg+g) mod 32, all distinct. BSTR=132 was a systematic 2-way conflict
//    on every B load (banks 4*tg+g), doubling B read cost on the crossbar.
//  * Single __syncthreads per k-stage: wait_group(1) -> sync -> issue loads
//    for stage s+2 -> compute stage s. The sync at iter s proves all warps
//    completed compute s-1, which protects slot (s+2)%3 == (s-1)%3; the old
//    trailing barrier was redundant. Loads now overlap the full compute stage.
//
// Engine (unchanged): raw-fp32-bits tf32 MMA (RZ truncation), product bias
// cancelled by TCORR folded into BN alpha; A fragments via ldmatrix.x4.b16.
// CTA 128x128, 8 warps (4x2), warp tile 32x64, 3-stage cp.async ring,
// 2 CTAs/SM.
// ---------------------------------------------------------------------------

#define FSZ   5
#define NB    256
#define LIN   512
#define CIN   64
#define UDIM  256
#define L1DIM 508
#define L2DIM 504
#define KCONV 320
#define KLOC  1280
#define BNEPS 0.001f
#define TCORR 1.0007045f              // cancels tf32 RZ-truncation product bias

#define NSTAGE  3
#define KC      32
#define ASTR    36                    // A smem row stride (floats); LDSM-clean
#define BSTR    136                   // B smem row stride; 136%32==8 -> no conflicts
#define A_BYTES (128 * ASTR * 4)      // 18432
#define B_BYTES (KC * BSTR * 4)       // 17408
#define STAGE_BYTES (A_BYTES + B_BYTES) // 35840
#define SMEM_ALPHA  0
#define SMEM_BETA   512
#define SMEM_STAGE0 1024
#define SMEM_TOTAL  (SMEM_STAGE0 + NSTAGE * STAGE_BYTES)  // 108544 (106 KB)

__device__ __align__(128) float g_y[(size_t)NB * L1DIM * UDIM];

// ---- PTX helpers -----------------------------------------------------------
__device__ __forceinline__ uint32_t smem_u32(const void* p) {
    uint32_t a;
    asm("{ .reg .u64 t; cvta.to.shared.u64 t, %1; cvt.u32.u64 %0, t; }"
        : "=r"(a) : "l"(p));
    return a;
}
#define CP_ASYNC16(dst, src) \
    asm volatile("cp.async.cg.shared.global [%0], [%1], 16;" \
                 :: "r"(dst), "l"(src) : "memory")
#define CP_COMMIT() asm volatile("cp.async.commit_group;" ::: "memory")
#define CP_WAIT1()  asm volatile("cp.async.wait_group 1;" ::: "memory")

__device__ __forceinline__ void ldsm_x4(uint32_t* r, uint32_t addr) {
    asm volatile("ldmatrix.sync.aligned.m8n8.x4.shared.b16 {%0,%1,%2,%3}, [%4];"
                 : "=r"(r[0]), "=r"(r[1]), "=r"(r[2]), "=r"(r[3]) : "r"(addr));
}
__device__ __forceinline__ void mma8(float* d, const uint32_t* a, const uint32_t* b) {
    asm volatile("mma.sync.aligned.m16n8k8.row.col.f32.tf32.tf32.f32 "
                 "{%0,%1,%2,%3}, {%4,%5,%6,%7}, {%8,%9}, {%0,%1,%2,%3};"
                 : "+f"(d[0]), "+f"(d[1]), "+f"(d[2]), "+f"(d[3])
                 : "r"(a[0]), "r"(a[1]), "r"(a[2]), "r"(a[3]),
                   "r"(b[0]), "r"(b[1]));
}

// one pipeline-stage load: A 128 rows x 32 floats + B 32 k-rows x 128 n
__device__ __forceinline__ void load_stage(uint32_t sb, const float* const* aptr,
                                           const float* bsrc0, int tid) {
    const int achunk = tid & 7;
    const int bchunk = tid & 31;
    #pragma unroll
    for (int p = 0; p < 4; p++) {
        int arow = (tid >> 3) + p * 32;
        uint32_t adst = sb + (uint32_t)(arow * ASTR + achunk * 4) * 4;
        CP_ASYNC16(adst, aptr[p] + achunk * 4);
    }
    const uint32_t sbB = sb + A_BYTES;
    #pragma unroll
    for (int p = 0; p < 4; p++) {
        int brow = (tid >> 5) + p * 8;
        uint32_t bdst = sbB + (uint32_t)(brow * BSTR + bchunk * 4) * 4;
        CP_ASYNC16(bdst, bsrc0 + (size_t)brow * UDIM + bchunk * 4);
    }
}

// ---------------------------------------------------------------------------
// MODE 0: conv stage.  grid (1016 m-tiles, 2 n-tiles).   A=x, out=g_y
// MODE 1: local stage. grid (2 m, 2 n, 504 l).           A=g_y, out=z
// ---------------------------------------------------------------------------
template <int MODE>
__global__ void __launch_bounds__(256, 2)
gemm_mma(const float* __restrict__ Ain, const float* __restrict__ Bmat0,
         const float* __restrict__ bias, const float* __restrict__ gg,
         const float* __restrict__ bbn, const float* __restrict__ mmn,
         const float* __restrict__ vvn, float* __restrict__ outp)
{
    extern __shared__ char smem[];
    const uint32_t sbase = smem_u32(smem);
    const uint32_t sb0 = sbase + SMEM_STAGE0;
    const int tid  = threadIdx.x;
    const int wid  = tid >> 5;
    const int lane = tid & 31;
    const int wm   = wid & 3;
    const int wn   = wid >> 2;
    const int g    = lane >> 2;
    const int tg   = lane & 3;

    const int S   = MODE ? (KLOC / KC) : (KCONV / KC);
    const int l   = MODE ? blockIdx.z : 0;
    const int mb0 = blockIdx.x * 128;
    const int n0  = blockIdx.y * 128;

    const float* Bmat = MODE ? (Bmat0 + (size_t)l * KLOC * UDIM) : Bmat0;
    float* out = MODE ? outp : g_y;

    // BN alpha/beta (alpha carries the tf32-truncation bias correction)
    if (tid < 128) {
        int n = n0 + tid;
        float a_ = gg[n] * rsqrtf(vvn[n] + BNEPS);
        float bi = MODE ? bias[(size_t)l * UDIM + n] : bias[n];
        ((float*)(smem + SMEM_ALPHA))[tid] = a_ * TCORR;
        ((float*)(smem + SMEM_BETA))[tid]  = bbn[n] + (bi - mmn[n]) * a_;
    }

    // per-thread A row pointers for the 4 load passes
    const float* aptr[4];
    #pragma unroll
    for (int p = 0; p < 4; p++) {
        int r = (tid >> 3) + p * 32;
        if (MODE) {
            aptr[p] = g_y + ((size_t)(mb0 + r) * L1DIM + l) * UDIM;
        } else {
            unsigned gm = mb0 + r;
            unsigned b  = gm / L1DIM;
            unsigned t  = gm - b * L1DIM;
            aptr[p] = Ain + ((size_t)b * LIN + t) * CIN;
        }
    }

    // pipeline prologue: stages 0 and 1
    #pragma unroll
    for (int p = 0; p < NSTAGE - 1; p++) {
        load_stage(sb0 + p * STAGE_BYTES, aptr, Bmat + (size_t)(p * KC) * UDIM + n0, tid);
        #pragma unroll
        for (int i = 0; i < 4; i++) aptr[i] += KC;
        CP_COMMIT();
    }

    float acc[2][8][4] = {};

    // ldmatrix lane->tile-row mapping for A fragments
    const int trow = (lane & 7) + ((lane >> 3) & 1) * 8;
    const int tk   = (lane >> 4) * 4;
    const int a_lm_off0 = (wm * 32 + 0  + trow) * ASTR + tk;
    const int a_lm_off1 = (wm * 32 + 16 + trow) * ASTR + tk;
    // scalar-B fragment base offset (floats)
    const int boff = tg * BSTR + wn * 64 + g;

    // Loop invariant: stage s = cp.async group s; committed before iter s's
    // commit = 2+s, so wait_group(1) makes group s resident. The single
    // barrier proves all warps finished compute s-1, protecting slot
    // (s+2)%3 == (s-1)%3 for the loads issued right after it.
    for (int s = 0; s < S; s++) {
        CP_WAIT1();
        __syncthreads();

        int pn = s + NSTAGE - 1;
        if (pn < S) {
            load_stage(sb0 + (pn % NSTAGE) * STAGE_BYTES, aptr,
                       Bmat + (size_t)(pn * KC) * UDIM + n0, tid);
            #pragma unroll
            for (int i = 0; i < 4; i++) aptr[i] += KC;
        }
        CP_COMMIT();          // uniform one group per iteration (may be empty)

        const uint32_t stg = sb0 + (s % NSTAGE) * STAGE_BYTES;
        const uint32_t aAddr0 = stg + (uint32_t)a_lm_off0 * 4;
        const uint32_t aAddr1 = stg + (uint32_t)a_lm_off1 * 4;
        const uint32_t* bB = (const uint32_t*)(smem + SMEM_STAGE0 +
                                               (s % NSTAGE) * STAGE_BYTES +
                                               A_BYTES) + boff;

        #pragma unroll
        for (int k8 = 0; k8 < KC / 8; k8++) {
            const int kk = k8 * 8;
            uint32_t af[2][4];
            ldsm_x4(af[0], aAddr0 + kk * 4);
            ldsm_x4(af[1], aAddr1 + kk * 4);
            uint32_t bf[8][2];
            #pragma unroll
            for (int jf = 0; jf < 8; jf++) {
                const uint32_t* p0 = bB + kk * BSTR + jf * 8;
                bf[jf][0] = p0[0];
                bf[jf][1] = p0[4 * BSTR];
            }
            #pragma unroll
            for (int mf = 0; mf < 2; mf++)
                #pragma unroll
                for (int jf = 0; jf < 8; jf++)
                    mma8(acc[mf][jf], af[mf], bf[jf]);
        }
    }

    // ---- epilogue: BN + ReLU, write out ----
    const float* al = (const float*)(smem + SMEM_ALPHA);
    const float* be = (const float*)(smem + SMEM_BETA);
    #pragma unroll
    for (int mf = 0; mf < 2; mf++) {
        int r0 = mb0 + wm * 32 + mf * 16 + g;   // and r0+8
        float* orow0;
        float* orow1;
        if (MODE) {
            orow0 = out + ((size_t)r0 * L2DIM + l) * UDIM;
            orow1 = out + ((size_t)(r0 + 8) * L2DIM + l) * UDIM;
        } else {
            orow0 = out + (size_t)r0 * UDIM;
            orow1 = out + (size_t)(r0 + 8) * UDIM;
        }
        #pragma unroll
        for (int jf = 0; jf < 8; jf++) {
            int cl = wn * 64 + jf * 8 + 2 * tg;
            float a0 = al[cl], a1 = al[cl + 1];
            float e0 = be[cl], e1 = be[cl + 1];
            float2 v0, v1;
            v0.x = fmaxf(acc[mf][jf][0] * a0 + e0, 0.f);
            v0.y = fmaxf(acc[mf][jf][1] * a1 + e1, 0.f);
            v1.x = fmaxf(acc[mf][jf][2] * a0 + e0, 0.f);
            v1.y = fmaxf(acc[mf][jf][3] * a1 + e1, 0.f);
            *(float2*)(orow0 + n0 + cl) = v0;
            *(float2*)(orow1 + n0 + cl) = v1;
        }
    }
}

// ---------------------------------------------------------------------------
extern "C" void kernel_launch(void* const* d_in, const int* in_sizes, int n_in,
                              void* d_out, int out_size)
{
    const float* x      = (const float*)d_in[0];
    const float* conv_w = (const float*)d_in[1];
    const float* conv_b = (const float*)d_in[2];
    const float* g1     = (const float*)d_in[3];
    const float* b1     = (const float*)d_in[4];
    const float* m1     = (const float*)d_in[5];
    const float* v1     = (const float*)d_in[6];
    const float* lw     = (const float*)d_in[7];
    const float* lb     = (const float*)d_in[8];
    const float* g2     = (const float*)d_in[9];
    const float* b2     = (const float*)d_in[10];
    const float* m2     = (const float*)d_in[11];
    const float* v2     = (const float*)d_in[12];
    float* z = (float*)d_out;

    static bool attr_set = false;
    if (!attr_set) {
        cudaFuncSetAttribute(gemm_mma<0>,
            cudaFuncAttributeMaxDynamicSharedMemorySize, SMEM_TOTAL);
        cudaFuncSetAttribute(gemm_mma<1>,
            cudaFuncAttributeMaxDynamicSharedMemorySize, SMEM_TOTAL);
        cudaFuncSetAttribute(gemm_mma<0>,
            cudaFuncAttributePreferredSharedMemoryCarveout, 100);
        cudaFuncSetAttribute(gemm_mma<1>,
            cudaFuncAttributePreferredSharedMemoryCarveout, 100);
        attr_set = true;
    }

    // Stage 1: M=130048 (1016 tiles), N=256 (2 tiles), K=320
    gemm_mma<0><<<dim3(1016, 2, 1), 256, SMEM_TOTAL>>>(
        x, conv_w, conv_b, g1, b1, m1, v1, nullptr);

    // Stage 2: per-l GEMMs, M=256 (2), N=256 (2), K=1280, l=504
    gemm_mma<1><<<dim3(2, 2, L2DIM), 256, SMEM_TOTAL>>>(
        nullptr, lw, lb, g2, b2, m2, v2, z);
}